// round 15
// baseline (speedup 1.0000x reference)
#include <cuda_runtime.h>
#include <cuda_bf16.h>

// SST: sst[b, k(b,f,t), t] += coeffs[b,f,t], k = clip(f + adj, 0, F-1),
// adj = signbit(x[t+1]) - signbit(x[t]) in {-1,0,+1} (adj=0 at t=T-1).
// k in {f-1, f, f+1} -> scatter re-expressed as rolling gather along F with
// three register accumulators (rows f-1, f, f+1).
//
// R15: bulk-async (TMA-path) producer. R7 spends ~35-40% of issue slots on
// per-thread LDGSTS staging (34 rows x 128 x rt8 per CTA) while DRAM sits at
// 72%. Here ONE cp.async.bulk per row (tid 0) stages 2064 B (row chunk + 16B
// neighbor tail) into a 4-pair SMEM ring; completion via mbarrier
// complete_tx; consumers do acquire-parity waits. Producer issue cost per
// CTA: ~51 instructions instead of ~4400. Ring depth (3 pairs in flight) and
// the 17-barrier cadence match the validated R7 pipeline.

constexpr int Bdim = 16;
constexpr int Fdim = 256;
constexpr int Tdim = 8192;
constexpr int TPB  = 128;
constexpr int NSEG = 8;
constexpr int SEG  = Fdim / NSEG;      // 32 output rows per CTA
constexpr int NR   = SEG + 2;          // rows touched incl. ghosts = 34
constexpr int NPAIR = NR / 2;          // 17 two-row stages
constexpr int NSLOT = 4;               // ring of 4 PAIR slots
constexpr int CHUNK = TPB * 16;        // 2048 B of row data per CTA
constexpr int ROWB  = CHUNK + 32;      // +16B tail +16B pad = 2080
constexpr int SLOTB = 2 * ROWB;        // 4160 B per pair slot

__device__ __forceinline__ int sgnbit(float x) {
    return (int)(__float_as_uint(x) >> 31);   // matches angle(): pi iff sign bit
}

__global__ __launch_bounds__(TPB, 13)
void sst_bulk_kernel(const float* __restrict__ in, float* __restrict__ out) {
    __shared__ __align__(16) unsigned char smbuf[NSLOT * SLOTB];   // 16.6 KB
    __shared__ __align__(8) unsigned long long mbar[NSLOT];

    const int tid = threadIdx.x;
    const int t0  = (blockIdx.x * TPB + tid) * 4;
    const int b   = blockIdx.y;
    const int fs  = blockIdx.z * SEG;
    const bool notlast = (t0 + 4) < Tdim;                        // per-thread
    const bool has_tail = (blockIdx.x + 1) * (CHUNK / 4) < Tdim; // per-CTA

    const size_t bofs = (size_t)b * Fdim * Tdim;
    const float* __restrict__ gbase = in + bofs + (size_t)blockIdx.x * (CHUNK / 4);
    float* __restrict__ obase = out + bofs + t0;

    const unsigned smem0 = (unsigned)__cvta_generic_to_shared(smbuf);
    const unsigned mb0   = (unsigned)__cvta_generic_to_shared(mbar);

    // producer (tid 0 only): stage pair p's two rows with bulk copies.
    // expect_tx is set to the exact byte count of the copies issued, so the
    // barrier flips precisely when this pair's data is resident.
    auto issue_pair = [&](int p) {
        if (tid == 0 && p < NPAIR) {
            const int f0 = fs - 1 + 2 * p;
            const int f1 = f0 + 1;
            const bool v0 = (unsigned)f0 < (unsigned)Fdim;
            const bool v1 = (unsigned)f1 < (unsigned)Fdim;
            const unsigned rb = CHUNK + (has_tail ? 16u : 0u);
            const unsigned tx = (v0 ? rb : 0u) + (v1 ? rb : 0u);
            const unsigned mb_s = mb0 + (unsigned)(p & 3) * 8u;
            const unsigned dst  = smem0 + (unsigned)(p & 3) * SLOTB;
            asm volatile("mbarrier.arrive.expect_tx.shared.b64 _, [%0], %1;"
                         :: "r"(mb_s), "r"(tx) : "memory");
            if (v0)
                asm volatile(
                    "cp.async.bulk.shared::cluster.global.mbarrier::complete_tx::bytes"
                    " [%0], [%1], %2, [%3];"
                    :: "r"(dst), "l"(gbase + (size_t)f0 * Tdim), "r"(rb), "r"(mb_s)
                    : "memory");
            if (v1)
                asm volatile(
                    "cp.async.bulk.shared::cluster.global.mbarrier::complete_tx::bytes"
                    " [%0], [%1], %2, [%3];"
                    :: "r"(dst + ROWB), "l"(gbase + (size_t)f1 * Tdim), "r"(rb), "r"(mb_s)
                    : "memory");
        }
    };

    // consumer wait: pair p resident (acquire). slot = p&3; nth reuse of a
    // slot is at p = slot + 4n, so phase parity = (p>>2)&1.
    auto wait_pair = [&](int p) {
        const unsigned mb_s = mb0 + (unsigned)(p & 3) * 8u;
        const unsigned parity = (unsigned)((p >> 2) & 1);
        unsigned done;
        asm volatile(
            "{\n\t.reg .pred q;\n\t"
            "mbarrier.try_wait.parity.acquire.cta.shared::cta.b64 q, [%1], %2;\n\t"
            "selp.b32 %0, 1, 0, q;\n\t}"
            : "=r"(done) : "r"(mb_s), "r"(parity) : "memory");
        if (!done) {
            asm volatile(
                "{\n\t.reg .pred q;\n\t"
                "W%=:\n\t"
                "mbarrier.try_wait.parity.acquire.cta.shared::cta.b64 q, [%0], %1, 0x989680;\n\t"
                "@q bra.uni D%=;\n\t"
                "bra.uni W%=;\n\t"
                "D%=:\n\t}"
                :: "r"(mb_s), "r"(parity) : "memory");
        }
    };

    // read row r from its slot: values + per-element shifts d in {-1,0,+1}.
    // neighbor t0+4 is at +16B, covered by the same bulk copy (tail bytes).
    auto load_row = [&](int r, float4& v, int& d0, int& d1, int& d2, int& d3) {
        const unsigned char* p =
            smbuf + ((r >> 1) & 3) * SLOTB + (r & 1) * ROWB + tid * 16;
        v = *reinterpret_cast<const float4*>(p);
        const float nx = *reinterpret_cast<const float*>(p + 16);
        const int s0 = sgnbit(v.x), s1 = sgnbit(v.y);
        const int s2 = sgnbit(v.z), s3 = sgnbit(v.w);
        const int s4 = sgnbit(nx);
        d0 = s1 - s0; d1 = s2 - s1; d2 = s3 - s2;
        d3 = notlast ? (s4 - s3) : 0;   // pad: adj=0 at t=T-1
    };

    // ---- init mbarriers (count 1: the producer's expect_tx arrive) ----
    if (tid == 0) {
        #pragma unroll
        for (int s = 0; s < NSLOT; ++s)
            asm volatile("mbarrier.init.shared.b64 [%0], 1;"
                         :: "r"(mb0 + s * 8u) : "memory");
        asm volatile("fence.proxy.async.shared::cta;" ::: "memory");
    }
    __syncthreads();

    // ---- pipeline prologue: pairs 0..2 in flight ----
    issue_pair(0);
    issue_pair(1);
    issue_pair(2);

    const float4 z = make_float4(0.f, 0.f, 0.f, 0.f);
    float4 A, B = z, C = z;
    float4 v;
    int d0, d1, d2, d3;

    // ---- pair 0: lower ghost row (fs-1) + first interior row (fs) ----
    // (refill of pair 3 goes to slot 3, untouched -> no barrier needed yet)
    issue_pair(3);
    wait_pair(0);
    if (fs > 0) {   // ghost: only its up-moves land in out[fs] (B)
        load_row(0, v, d0, d1, d2, d3);
        B.x += (d0 > 0) ? v.x : 0.f;
        B.y += (d1 > 0) ? v.y : 0.f;
        B.z += (d2 > 0) ? v.z : 0.f;
        B.w += (d3 > 0) ? v.w : 0.f;
    }
    load_row(1, v, d0, d1, d2, d3);
    if (fs == 0) {   // clip at lower F edge: down-moves stay in row 0
        d0 = max(d0, 0); d1 = max(d1, 0); d2 = max(d2, 0); d3 = max(d3, 0);
    }
    // A-part (out[fs-1]) belongs to the neighbor block: discard.
    B.x += (d0 == 0) ? v.x : 0.f;  C.x += (d0 > 0) ? v.x : 0.f;
    B.y += (d1 == 0) ? v.y : 0.f;  C.y += (d1 > 0) ? v.y : 0.f;
    B.z += (d2 == 0) ? v.z : 0.f;  C.z += (d2 > 0) ? v.z : 0.f;
    B.w += (d3 == 0) ? v.w : 0.f;  C.w += (d3 > 0) ? v.w : 0.f;

    // ---- pairs 1..15: branch-free interior (rows 2..31 = f fs+1..fs+30) ----
    float* orow = obase + (size_t)fs * Tdim;
    #pragma unroll 1
    for (int p = 1; p < NPAIR - 1; ++p) {
        // refill slot (p+3)&3 == (p-1)&3: all threads consumed pair p-1 in
        // the previous iteration; this barrier makes that consumption global
        // before tid 0 overwrites the slot.
        __syncthreads();
        issue_pair(p + 3);
        wait_pair(p);
        #pragma unroll
        for (int half = 0; half < 2; ++half) {
            const int r = 2 * p + half;
            A = B; B = C; C = z;
            load_row(r, v, d0, d1, d2, d3);
            A.x += (d0 < 0) ? v.x : 0.f;
            B.x += (d0 == 0) ? v.x : 0.f;
            C.x += (d0 > 0) ? v.x : 0.f;
            A.y += (d1 < 0) ? v.y : 0.f;
            B.y += (d1 == 0) ? v.y : 0.f;
            C.y += (d1 > 0) ? v.y : 0.f;
            A.z += (d2 < 0) ? v.z : 0.f;
            B.z += (d2 == 0) ? v.z : 0.f;
            C.z += (d2 > 0) ? v.z : 0.f;
            A.w += (d3 < 0) ? v.w : 0.f;
            B.w += (d3 == 0) ? v.w : 0.f;
            C.w += (d3 > 0) ? v.w : 0.f;
            *reinterpret_cast<float4*>(orow) = A;   // out[f-1] complete
            orow += Tdim;
        }
    }

    // ---- pair 16: last interior row (f = fs+SEG-1) + upper ghost ----
    __syncthreads();          // pair 15 fully consumed (no refill remains)
    wait_pair(NPAIR - 1);
    A = B; B = C;
    load_row(NR - 2, v, d0, d1, d2, d3);
    if (fs + SEG == Fdim) {   // clip at upper F edge: up-moves stay
        d0 = min(d0, 0); d1 = min(d1, 0); d2 = min(d2, 0); d3 = min(d3, 0);
    }
    // C-part (out[fs+SEG]) belongs to the neighbor block: discard.
    A.x += (d0 < 0) ? v.x : 0.f;  B.x += (d0 == 0) ? v.x : 0.f;
    A.y += (d1 < 0) ? v.y : 0.f;  B.y += (d1 == 0) ? v.y : 0.f;
    A.z += (d2 < 0) ? v.z : 0.f;  B.z += (d2 == 0) ? v.z : 0.f;
    A.w += (d3 < 0) ? v.w : 0.f;  B.w += (d3 == 0) ? v.w : 0.f;
    *reinterpret_cast<float4*>(orow) = A;       // out[fs+SEG-2]
    orow += Tdim;

    if (fs + SEG < Fdim) {   // upper ghost: only its down-moves in B
        load_row(NR - 1, v, d0, d1, d2, d3);
        B.x += (d0 < 0) ? v.x : 0.f;
        B.y += (d1 < 0) ? v.y : 0.f;
        B.z += (d2 < 0) ? v.z : 0.f;
        B.w += (d3 < 0) ? v.w : 0.f;
    }
    *reinterpret_cast<float4*>(orow) = B;       // out[fs+SEG-1] complete
}

extern "C" void kernel_launch(void* const* d_in, const int* in_sizes, int n_in,
                              void* d_out, int out_size) {
    const float* coeffs = (const float*)d_in[0];
    float* out = (float*)d_out;

    dim3 grid(Tdim / 4 / TPB, Bdim, NSEG);   // (16, 16, 8) = 2048 CTAs
    dim3 block(TPB);
    sst_bulk_kernel<<<grid, block>>>(coeffs, out);
}

// round 16
// speedup vs baseline: 1.0176x; 1.0176x over previous
#include <cuda_runtime.h>
#include <cuda_bf16.h>

// SST: sst[b, k(b,f,t), t] += coeffs[b,f,t], k = clip(f + adj, 0, F-1),
// adj = signbit(x[t+1]) - signbit(x[t]) in {-1,0,+1} (adj=0 at t=T-1).
// k in {f-1, f, f+1} -> scatter re-expressed as rolling gather along F with
// three register accumulators (rows f-1, f, f+1). cp.async SMEM ring covers
// DRAM latency; two rows per pipeline stage (17 block barriers per CTA).
//
// FINAL = R7, best-measured configuration (bench 47.68us; kernel 38.2-38.8us
// at ~5.8 TB/s effective = mixed R/W HBM3e sustained ceiling — confirmed by
// direct intervention in R15: removing issue pressure via cp.async.bulk left
// DRAM% unchanged). Traffic is within ~5% of minimum. Refuted alternatives:
// NSEG=4 @ grid1024 (occupancy, R6), barrier-free per-thread pipeline (R8),
// st.global.cs (neutral, R9), float2 strips (L1tex-bound, R11), TPB=256
// (shallow pipeline, R13), bulk-async producer (no DRAM gain, R15).
// Invariants: 16B per thread per memory op; >=3 stages in flight.

constexpr int Bdim = 16;
constexpr int Fdim = 256;
constexpr int Tdim = 8192;
constexpr int TPB  = 128;
constexpr int NSEG = 8;
constexpr int SEG  = Fdim / NSEG;      // 32 output rows per CTA
constexpr int NR   = SEG + 2;          // rows touched incl. ghosts = 34
constexpr int NPAIR = NR / 2;          // 17 two-row stages
constexpr int NSLOT = 8;               // ring of 8 row slots = 4 pairs
constexpr int CHUNK = TPB * 16;        // 2048 B of row data per CTA
constexpr int STAGE = CHUNK + 32;      // +16B neighbor tail +16B pad = 2080

__device__ __forceinline__ int sgnbit(float x) {
    return (int)(__float_as_uint(x) >> 31);   // matches angle(): pi iff sign bit
}

__global__ __launch_bounds__(TPB, 13)
void sst_pipe_kernel(const float* __restrict__ in, float* __restrict__ out) {
    __shared__ __align__(16) unsigned char smbuf[NSLOT * STAGE];

    const int tid = threadIdx.x;
    const int t0  = (blockIdx.x * TPB + tid) * 4;
    const int b   = blockIdx.y;
    const int fs  = blockIdx.z * SEG;
    const bool notlast = (t0 + 4) < Tdim;                        // per-thread
    const bool has_tail = (blockIdx.x + 1) * (CHUNK / 4) < Tdim; // per-CTA

    const size_t bofs = (size_t)b * Fdim * Tdim;
    const float* __restrict__ gbase = in + bofs + (size_t)blockIdx.x * (CHUNK / 4);
    float* __restrict__ obase = out + bofs + t0;

    const unsigned smem0 = (unsigned)__cvta_generic_to_shared(smbuf);

    // copy one row into its ring slot (16B per thread + 16B tail via tid 0)
    auto issue_row = [&](int r) {
        const int f = fs - 1 + r;
        if ((unsigned)f < (unsigned)Fdim) {
            const float* src = gbase + (size_t)f * Tdim;
            const unsigned dst = smem0 + (r % NSLOT) * STAGE;
            asm volatile("cp.async.cg.shared.global [%0], [%1], 16;"
                         :: "r"(dst + tid * 16), "l"(src + tid * 4) : "memory");
            if (tid == 0 && has_tail) {
                asm volatile("cp.async.cg.shared.global [%0], [%1], 16;"
                             :: "r"(dst + CHUNK), "l"(src + CHUNK / 4) : "memory");
            }
        }
    };

    // one commit group per PAIR; always commits (uniform group counting --
    // empty commits at the tail keep wait_group semantics exact; R4 lesson)
    auto issue_pair = [&](int p) {
        if (p < NPAIR) {
            issue_row(2 * p);
            issue_row(2 * p + 1);
        }
        asm volatile("cp.async.commit_group;" ::: "memory");
    };

    // make pair p resident for all threads, then refill one pair slot.
    // commits before acquire(p) = 3 + p; wait_group 2 -> p+1 pairs done.
    auto acquire = [&](int p) {
        asm volatile("cp.async.wait_group 2;" ::: "memory");
        __syncthreads();
        issue_pair(p + 3);
    };

    // read row r from SMEM: values + per-element shifts d in {-1,0,+1}
    auto load_row = [&](int r, float4& v, int& d0, int& d1, int& d2, int& d3) {
        const unsigned char* p = smbuf + (r % NSLOT) * STAGE + tid * 16;
        v = *reinterpret_cast<const float4*>(p);
        const float nx = *reinterpret_cast<const float*>(p + 16);
        const int s0 = sgnbit(v.x), s1 = sgnbit(v.y);
        const int s2 = sgnbit(v.z), s3 = sgnbit(v.w);
        const int s4 = sgnbit(nx);
        d0 = s1 - s0; d1 = s2 - s1; d2 = s3 - s2;
        d3 = notlast ? (s4 - s3) : 0;   // pad: adj=0 at t=T-1
    };

    // ---- pipeline prologue: pairs 0..2 (rows 0..5) ----
    issue_pair(0);
    issue_pair(1);
    issue_pair(2);

    const float4 z = make_float4(0.f, 0.f, 0.f, 0.f);
    float4 A, B = z, C = z;
    float4 v;
    int d0, d1, d2, d3;

    // ---- pair 0: lower ghost row (fs-1) + first interior row (fs) ----
    acquire(0);
    if (fs > 0) {   // ghost: only its up-moves land in out[fs] (B)
        load_row(0, v, d0, d1, d2, d3);
        B.x += (d0 > 0) ? v.x : 0.f;
        B.y += (d1 > 0) ? v.y : 0.f;
        B.z += (d2 > 0) ? v.z : 0.f;
        B.w += (d3 > 0) ? v.w : 0.f;
    }
    load_row(1, v, d0, d1, d2, d3);
    if (fs == 0) {   // clip at lower F edge: down-moves stay in row 0
        d0 = max(d0, 0); d1 = max(d1, 0); d2 = max(d2, 0); d3 = max(d3, 0);
    }
    // A-part (out[fs-1]) belongs to the neighbor block: discard.
    B.x += (d0 == 0) ? v.x : 0.f;  C.x += (d0 > 0) ? v.x : 0.f;
    B.y += (d1 == 0) ? v.y : 0.f;  C.y += (d1 > 0) ? v.y : 0.f;
    B.z += (d2 == 0) ? v.z : 0.f;  C.z += (d2 > 0) ? v.z : 0.f;
    B.w += (d3 == 0) ? v.w : 0.f;  C.w += (d3 > 0) ? v.w : 0.f;

    // ---- pairs 1..15: branch-free interior (rows 2..31 = f fs+1..fs+30) ----
    float* orow = obase + (size_t)fs * Tdim;
    #pragma unroll 1
    for (int p = 1; p < NPAIR - 1; ++p) {
        acquire(p);
        #pragma unroll
        for (int half = 0; half < 2; ++half) {
            const int r = 2 * p + half;
            A = B; B = C; C = z;
            load_row(r, v, d0, d1, d2, d3);
            A.x += (d0 < 0) ? v.x : 0.f;
            B.x += (d0 == 0) ? v.x : 0.f;
            C.x += (d0 > 0) ? v.x : 0.f;
            A.y += (d1 < 0) ? v.y : 0.f;
            B.y += (d1 == 0) ? v.y : 0.f;
            C.y += (d1 > 0) ? v.y : 0.f;
            A.z += (d2 < 0) ? v.z : 0.f;
            B.z += (d2 == 0) ? v.z : 0.f;
            C.z += (d2 > 0) ? v.z : 0.f;
            A.w += (d3 < 0) ? v.w : 0.f;
            B.w += (d3 == 0) ? v.w : 0.f;
            C.w += (d3 > 0) ? v.w : 0.f;
            *reinterpret_cast<float4*>(orow) = A;   // out[f-1] complete
            orow += Tdim;
        }
    }

    // ---- pair 16: last interior row (f = fs+SEG-1) + upper ghost ----
    acquire(NPAIR - 1);
    A = B; B = C;
    load_row(NR - 2, v, d0, d1, d2, d3);
    if (fs + SEG == Fdim) {   // clip at upper F edge: up-moves stay
        d0 = min(d0, 0); d1 = min(d1, 0); d2 = min(d2, 0); d3 = min(d3, 0);
    }
    // C-part (out[fs+SEG]) belongs to the neighbor block: discard.
    A.x += (d0 < 0) ? v.x : 0.f;  B.x += (d0 == 0) ? v.x : 0.f;
    A.y += (d1 < 0) ? v.y : 0.f;  B.y += (d1 == 0) ? v.y : 0.f;
    A.z += (d2 < 0) ? v.z : 0.f;  B.z += (d2 == 0) ? v.z : 0.f;
    A.w += (d3 < 0) ? v.w : 0.f;  B.w += (d3 == 0) ? v.w : 0.f;
    *reinterpret_cast<float4*>(orow) = A;       // out[fs+SEG-2]
    orow += Tdim;

    if (fs + SEG < Fdim) {   // upper ghost: only its down-moves in B
        load_row(NR - 1, v, d0, d1, d2, d3);
        B.x += (d0 < 0) ? v.x : 0.f;
        B.y += (d1 < 0) ? v.y : 0.f;
        B.z += (d2 < 0) ? v.z : 0.f;
        B.w += (d3 < 0) ? v.w : 0.f;
    }
    *reinterpret_cast<float4*>(orow) = B;       // out[fs+SEG-1] complete
}

extern "C" void kernel_launch(void* const* d_in, const int* in_sizes, int n_in,
                              void* d_out, int out_size) {
    const float* coeffs = (const float*)d_in[0];
    float* out = (float*)d_out;

    dim3 grid(Tdim / 4 / TPB, Bdim, NSEG);   // (16, 16, 8) = 2048 CTAs
    dim3 block(TPB);
    sst_pipe_kernel<<<grid, block>>>(coeffs, out);
}